// round 13
// baseline (speedup 1.0000x reference)
#include <cuda_runtime.h>
#include <cuda_bf16.h>
#include <stdint.h>
#include <math.h>

#define NN 4096
#define MM 8192
#define DD 128

typedef __nv_bfloat16 bf16;

// ----------------- device scratch (no allocations allowed) -----------------
__device__ bf16  g_Phi[(size_t)MM * MM];
__device__ bf16  g_Xuh[MM * DD];
__device__ bf16  g_Yth[DD * MM];
__device__ bf16  g_Xth[DD * NN];
__device__ bf16  g_W1h[DD * DD];
__device__ bf16  g_W2h[DD * DD];
__device__ bf16  g_Wuh[(size_t)NN * NN];
__device__ float g_part[8 * NN * DD];     // = 4*MM*DD floats
__device__ float g_degp[64 * MM];
__device__ float g_dinv[MM];
__device__ float g_rsA[NN];
__device__ unsigned g_cnt[64];            // split-k arrival counters (self-reset)

// ----------------------------- helpers ------------------------------------
__device__ __forceinline__ uint32_t s2u(const void* p) {
    uint32_t a;
    asm("{ .reg .u64 t; cvta.to.shared.u64 t, %1; cvt.u32.u64 %0, t; }"
        : "=r"(a) : "l"(p));
    return a;
}
#define SW128(o) ((o) ^ (((o) >> 3) & 0x70))

#define CPA(dst, src) asm volatile( \
    "cp.async.cg.shared.global [%0], [%1], 16;" :: "r"(dst), "l"(src))
#define CPCOMMIT() asm volatile("cp.async.commit_group;" ::: "memory")
#define CPWAIT(n)  asm volatile("cp.async.wait_group %0;" :: "n"(n) : "memory")

__device__ __forceinline__ void ldmx4(uint32_t* r, uint32_t a) {
    asm volatile("ldmatrix.sync.aligned.m8n8.x4.shared.b16 {%0,%1,%2,%3}, [%4];"
        : "=r"(r[0]), "=r"(r[1]), "=r"(r[2]), "=r"(r[3]) : "r"(a));
}
__device__ __forceinline__ void ldmx2(uint32_t* r, uint32_t a) {
    asm volatile("ldmatrix.sync.aligned.m8n8.x2.shared.b16 {%0,%1}, [%2];"
        : "=r"(r[0]), "=r"(r[1]) : "r"(a));
}
__device__ __forceinline__ void mma16816(float* c, const uint32_t* a, const uint32_t* b) {
    asm volatile(
        "mma.sync.aligned.m16n8k16.row.col.f32.bf16.bf16.f32 "
        "{%0,%1,%2,%3}, {%4,%5,%6,%7}, {%8,%9}, {%0,%1,%2,%3};"
        : "+f"(c[0]), "+f"(c[1]), "+f"(c[2]), "+f"(c[3])
        : "r"(a[0]), "r"(a[1]), "r"(a[2]), "r"(a[3]), "r"(b[0]), "r"(b[1]));
}

__device__ __forceinline__ uint32_t pkh(float a, float b) {
    return (uint32_t)__bfloat16_as_ushort(__float2bfloat16(a)) |
           ((uint32_t)__bfloat16_as_ushort(__float2bfloat16(b)) << 16);
}
__device__ __forceinline__ float sigm(float x) {
    return __fdividef(1.0f, 1.0f + __expf(-x));
}

#define SGL_SMEM 65536
#define SF_OFF   65536
#define RED_OFF  (65536 + 128 * 69 * 4)
#define XXT_SMEM (65536 + 128 * 69 * 4 + 1024)

// ===========================================================================
// adj_single (bf16): part[y] = A @ B^T. CTA 128x128, 2 CTAs/SM, warps 64x32.
// If xout != null (ksplit must be 4): last-arriving CTA per row-block fuses
// the split-k reduction + dinv*acc + bias + relu -> bf16 xout, then resets
// its counter for the next launch. Deterministic (fixed summation order).
// ===========================================================================
__device__ __forceinline__ void sgl_load(uint32_t sb, uint32_t stage,
    const bf16* Ah, int lda, const bf16* Bh, int ldb, int m0, int k0, int tid)
{
    uint32_t base = sb + stage * 32768u;
#pragma unroll
    for (int p = 0; p < 8; p++) {
        int idx = tid + p * 256;
        int mat = idx >> 10, w = idx & 1023, r = w >> 3, cg = w & 7;
        const bf16* s = mat ? (Bh + (size_t)r * ldb + k0 + cg * 8)
                            : (Ah + (size_t)(m0 + r) * lda + k0 + cg * 8);
        CPA(base + mat * 16384u + SW128(r * 128 + cg * 16), s);
    }
}

__global__ __launch_bounds__(256, 2) void adj_single(
    const bf16* __restrict__ Ah, int lda,
    const bf16* __restrict__ Bh, int ldb,
    float* __restrict__ part, int kcta, int pstride,
    const float* __restrict__ dinv, const float* __restrict__ bias,
    bf16* __restrict__ xout, unsigned* __restrict__ cnt)
{
    extern __shared__ char smem[];
    const uint32_t sb = s2u(smem);
    const int tid = threadIdx.x, wid = tid >> 5, lane = tid & 31;
    const int wm = wid & 1, wn = wid >> 1;
    const int m0 = blockIdx.x * 128;
    const int k0b = blockIdx.y * kcta;
    const int NT = kcta >> 6;

    float acc[4][4][4];
#pragma unroll
    for (int i = 0; i < 4; i++)
#pragma unroll
        for (int j = 0; j < 4; j++)
#pragma unroll
            for (int e = 0; e < 4; e++) acc[i][j][e] = 0.0f;

    const uint32_t swz = (uint32_t)(lane & 7) << 4;
    uint32_t arow[4], brow[4];
#pragma unroll
    for (int t = 0; t < 4; t++) {
        arow[t] = (uint32_t)((wm * 64 + t * 16 + (lane & 15)) * 128);
        brow[t] = (uint32_t)((wn * 32 + t * 8 + (lane & 7)) * 128);
    }
    const uint32_t akh = (uint32_t)((lane >> 4) * 16);
    const uint32_t bkh = (uint32_t)(((lane >> 3) & 1) * 16);

    sgl_load(sb, 0, Ah, lda, Bh, ldb, m0, k0b, tid);
    CPCOMMIT();

    for (int kt = 0; kt < NT; kt++) {
        if (kt + 1 < NT) {
            sgl_load(sb, (kt + 1) & 1, Ah, lda, Bh, ldb, m0, k0b + (kt + 1) * 64, tid);
            CPCOMMIT();
            CPWAIT(1);
        } else {
            CPWAIT(0);
        }
        __syncthreads();

        uint32_t st = sb + (uint32_t)(kt & 1) * 32768u;
#pragma unroll
        for (int ks = 0; ks < 4; ks++) {
            uint32_t axk = ((uint32_t)(ks * 32) + akh) ^ swz;
            uint32_t bxk = ((uint32_t)(ks * 32) + bkh) ^ swz;
            uint32_t ah[4][4], bh[4][2];
#pragma unroll
            for (int t = 0; t < 4; t++) {
                ldmx4(ah[t], st + arow[t] + axk);
                ldmx2(bh[t], st + 16384u + brow[t] + bxk);
            }
#pragma unroll
            for (int tm = 0; tm < 4; tm++)
#pragma unroll
                for (int tn = 0; tn < 4; tn++)
                    mma16816(acc[tm][tn], ah[tm], bh[tn]);
        }
        __syncthreads();
    }

    float* dst = part + (size_t)blockIdx.y * pstride + (size_t)m0 * 128;
#pragma unroll
    for (int tm = 0; tm < 4; tm++)
#pragma unroll
        for (int tn = 0; tn < 4; tn++) {
            int r0 = wm * 64 + tm * 16 + (lane >> 2);
            int c0 = wn * 32 + tn * 8 + 2 * (lane & 3);
            *(float2*)(dst + (size_t)r0 * 128 + c0) =
                make_float2(acc[tm][tn][0], acc[tm][tn][1]);
            *(float2*)(dst + (size_t)(r0 + 8) * 128 + c0) =
                make_float2(acc[tm][tn][2], acc[tm][tn][3]);
        }

    if (!xout) return;

    // ---- fused split-k reduction (ksplit == 4) ----
    __shared__ unsigned s_old;
    __syncthreads();                       // all partial stores issued
    if (tid == 0) {
        __threadfence();                   // make partial visible
        s_old = atomicAdd(&cnt[blockIdx.x], 1u);
    }
    __syncthreads();
    if (s_old != 3u) return;               // not the last arrival

    __threadfence();                       // acquire: see all partials
    const float4* p0 = (const float4*)(part + (size_t)m0 * 128);
    const float4* p1 = (const float4*)(part + (size_t)pstride + (size_t)m0 * 128);
    const float4* p2 = (const float4*)(part + (size_t)2 * pstride + (size_t)m0 * 128);
    const float4* p3 = (const float4*)(part + (size_t)3 * pstride + (size_t)m0 * 128);
#pragma unroll
    for (int u = 0; u < 16; u++) {
        int idx = tid + u * 256;           // over 4096 float4 groups
        int row = idx >> 5, c = (idx & 31) * 4;
        float4 a = p0[idx], b = p1[idx], d = p2[idx], e = p3[idx];
        float di = dinv[m0 + row];
        float4 bb = *(const float4*)(bias + c);
        float v0 = fmaxf(di * (a.x + b.x + d.x + e.x) + bb.x, 0.0f);
        float v1 = fmaxf(di * (a.y + b.y + d.y + e.y) + bb.y, 0.0f);
        float v2 = fmaxf(di * (a.z + b.z + d.z + e.z) + bb.z, 0.0f);
        float v3 = fmaxf(di * (a.w + b.w + d.w + e.w) + bb.w, 0.0f);
        *(uint2*)(xout + (size_t)(m0 + row) * 128 + c) =
            make_uint2(pkh(v0, v1), pkh(v2, v3));
    }
    if (tid == 0) cnt[blockIdx.x] = 0u;    // self-reset for next launch
}

// ===========================================================================
// xxt_single: sigmoid(X X^T), X bf16 [n x 128], 128x128 tile pairs with
// DIAGONAL-LAST ordering. mode 0: bf16 into Ph (+mirror) + deg partials.
// mode 1: fp32 into Pf (+mirror).
// ===========================================================================
__global__ __launch_bounds__(256, 2) void xxt_single(
    const bf16* __restrict__ Xh, int ooff, int ndiag,
    bf16* __restrict__ Ph, float* __restrict__ Pf,
    float* __restrict__ degp, int mode)
{
    extern __shared__ char smem[];
    const uint32_t sb = s2u(smem);
    const int tid = threadIdx.x, wid = tid >> 5, lane = tid & 31;
    const int wm = wid & 1, wn = wid >> 1;

    int b = blockIdx.x;
    const int OFFD = ndiag * (ndiag - 1) / 2;
    int bi, bj;
    if (b < OFFD) {
        bj = (int)((1.0f + sqrtf(8.0f * (float)b + 1.0f)) * 0.5f);
        while (bj * (bj - 1) / 2 > b) bj--;
        while ((bj + 1) * bj / 2 <= b) bj++;
        bi = b - bj * (bj - 1) / 2;
    } else {
        bi = bj = b - OFFD;
    }

#pragma unroll
    for (int p = 0; p < 16; p++) {
        int idx = tid + p * 256;
        int mat = idx >> 11, w = idx & 2047, kb = w >> 10, ww = w & 1023;
        int r = ww >> 3, cg = ww & 7;
        int rb = (mat ? bj : bi) * 128;
        CPA(sb + (uint32_t)mat * 32768u + (uint32_t)kb * 16384u +
                SW128(r * 128 + cg * 16),
            Xh + (size_t)(rb + r) * 128 + kb * 64 + cg * 8);
    }
    CPCOMMIT();

    float acc[4][4][4];
#pragma unroll
    for (int i = 0; i < 4; i++)
#pragma unroll
        for (int j = 0; j < 4; j++)
#pragma unroll
            for (int e = 0; e < 4; e++) acc[i][j][e] = 0.0f;

    const uint32_t swz = (uint32_t)(lane & 7) << 4;
    uint32_t arow[4], brow[4];
#pragma unroll
    for (int t = 0; t < 4; t++) {
        arow[t] = (uint32_t)((wm * 64 + t * 16 + (lane & 15)) * 128);
        brow[t] = (uint32_t)((wn * 32 + t * 8 + (lane & 7)) * 128);
    }
    const uint32_t akh = (uint32_t)((lane >> 4) * 16);
    const uint32_t bkh = (uint32_t)(((lane >> 3) & 1) * 16);

    CPWAIT(0);
    __syncthreads();

#pragma unroll
    for (int ks = 0; ks < 8; ks++) {
        uint32_t kbo = (uint32_t)(ks >> 2) * 16384u;
        uint32_t axk = ((uint32_t)((ks & 3) * 32) + akh) ^ swz;
        uint32_t bxk = ((uint32_t)((ks & 3) * 32) + bkh) ^ swz;
        uint32_t ah[4][4], bh[4][2];
#pragma unroll
        for (int t = 0; t < 4; t++) {
            ldmx4(ah[t], sb + kbo + arow[t] + axk);
            ldmx2(bh[t], sb + 32768u + kbo + brow[t] + bxk);
        }
#pragma unroll
        for (int tm = 0; tm < 4; tm++)
#pragma unroll
            for (int tn = 0; tn < 4; tn++)
                mma16816(acc[tm][tn], ah[tm], bh[tn]);
    }

    const int gi0 = ooff + bi * 128;
    const int gj0 = ooff + bj * 128;
    float* sf = (float*)(smem + SF_OFF);      // [128][69]
    float* sred = (float*)(smem + RED_OFF);   // [256]

    float sdeg = 0.0f;

#pragma unroll
    for (int h = 0; h < 2; h++) {
        __syncthreads();
        if ((wn >> 1) == h) {
#pragma unroll
            for (int tm = 0; tm < 4; tm++)
#pragma unroll
                for (int tn = 0; tn < 4; tn++) {
                    int r0 = wm * 64 + tm * 16 + (lane >> 2);
                    int cs = (wn & 1) * 32 + tn * 8 + 2 * (lane & 3);
                    sf[r0 * 69 + cs]           = sigm(acc[tm][tn][0]);
                    sf[r0 * 69 + cs + 1]       = sigm(acc[tm][tn][1]);
                    sf[(r0 + 8) * 69 + cs]     = sigm(acc[tm][tn][2]);
                    sf[(r0 + 8) * 69 + cs + 1] = sigm(acc[tm][tn][3]);
                }
        }
        __syncthreads();

        if (mode == 0) {
            const int r = tid & 127;
            const int ch = (tid >> 7) * 32;
            float v[32];
#pragma unroll
            for (int c = 0; c < 32; c++) {
                v[c] = sf[r * 69 + ch + c];
                sdeg += v[c];
            }
            bf16* drow = Ph + (size_t)(gi0 + r) * MM + gj0 + h * 64 + ch;
#pragma unroll
            for (int q = 0; q < 4; q++) {
                uint4 o;
                o.x = pkh(v[q*8+0], v[q*8+1]); o.y = pkh(v[q*8+2], v[q*8+3]);
                o.z = pkh(v[q*8+4], v[q*8+5]); o.w = pkh(v[q*8+6], v[q*8+7]);
                *(uint4*)(drow + q * 8) = o;
            }
            if (bi != bj) {
                const int mc = tid & 63;
                const int mchunk = tid >> 6;
                float w[32];
                float ms = 0.0f;
#pragma unroll
                for (int c = 0; c < 32; c++) {
                    w[c] = sf[(mchunk * 32 + c) * 69 + mc];
                    ms += w[c];
                }
                bf16* mrow = Ph + (size_t)(gj0 + h * 64 + mc) * MM + gi0 + mchunk * 32;
#pragma unroll
                for (int q = 0; q < 4; q++) {
                    uint4 o;
                    o.x = pkh(w[q*8+0], w[q*8+1]); o.y = pkh(w[q*8+2], w[q*8+3]);
                    o.z = pkh(w[q*8+4], w[q*8+5]); o.w = pkh(w[q*8+6], w[q*8+7]);
                    *(uint4*)(mrow + q * 8) = o;
                }
                sred[tid] = ms;
                __syncthreads();
                if (degp && tid < 64)
                    degp[(size_t)bi * MM + gj0 + h * 64 + tid] =
                        sred[tid] + sred[tid + 64] + sred[tid + 128] + sred[tid + 192];
            }
        } else {
            const int r = tid >> 1;
            const int ch = (tid & 1) * 32;
            const int mc = tid >> 2;
            const int mchunk = tid & 3;
            float* drow = Pf + (size_t)(gi0 + r) * MM + gj0 + h * 64 + ch;
#pragma unroll
            for (int q = 0; q < 8; q++) {
                float4 o = make_float4(sf[r * 69 + ch + q*4], sf[r * 69 + ch + q*4+1],
                                       sf[r * 69 + ch + q*4+2], sf[r * 69 + ch + q*4+3]);
                *(float4*)(drow + q * 4) = o;
            }
            if (bi != bj) {
                float* mrow = Pf + (size_t)(gj0 + h * 64 + mc) * MM + gi0 + mchunk * 32;
#pragma unroll
                for (int q = 0; q < 8; q++) {
                    float4 o = make_float4(sf[(mchunk*32 + q*4+0) * 69 + mc],
                                           sf[(mchunk*32 + q*4+1) * 69 + mc],
                                           sf[(mchunk*32 + q*4+2) * 69 + mc],
                                           sf[(mchunk*32 + q*4+3) * 69 + mc]);
                    *(float4*)(mrow + q * 4) = o;
                }
            }
        }
    }

    if (mode == 0 && degp) {
        __syncthreads();
        sred[tid] = sdeg;
        __syncthreads();
        if (tid < 128)
            degp[(size_t)bj * MM + gi0 + tid] = sred[tid] + sred[tid + 128];
    }
}

// ===========================================================================
// smallw: Yth[c][j] = dinv[j] * (Xu[j,:] @ W^T[c,:]). Fused small GEMM +
// scale + transpose; optionally folds deg_reduce (degp != null).
// ===========================================================================
__global__ __launch_bounds__(256, 2) void smallw(
    const bf16* __restrict__ Xuh, const bf16* __restrict__ Wt,
    float* __restrict__ dinv, const float* __restrict__ degp,
    bf16* __restrict__ yth)
{
    extern __shared__ char smem[];
    const uint32_t sb = s2u(smem);
    const int tid = threadIdx.x, wid = tid >> 5, lane = tid & 31;
    const int wm = wid & 1, wn = wid >> 1;
    const int m0 = blockIdx.x * 128;
    float* sdv = (float*)(smem + RED_OFF);   // [128]

#pragma unroll
    for (int p = 0; p < 16; p++) {
        int idx = tid + p * 256;
        int mat = idx >> 11, w = idx & 2047, kb = w >> 10, ww = w & 1023;
        int r = ww >> 3, cg = ww & 7;
        const bf16* s = mat ? (Wt + (size_t)r * 128 + kb * 64 + cg * 8)
                            : (Xuh + (size_t)(m0 + r) * 128 + kb * 64 + cg * 8);
        CPA(sb + (uint32_t)mat * 32768u + (uint32_t)kb * 16384u +
                SW128(r * 128 + cg * 16), s);
    }
    CPCOMMIT();

    if (tid < 128) {
        float dv;
        if (degp) {
            float d = 0.0f;
#pragma unroll
            for (int s = 0; s < 64; s++) d += degp[(size_t)s * MM + m0 + tid];
            dv = d > 0.0f ? rsqrtf(d) : 0.0f;
            dinv[m0 + tid] = dv;
        } else {
            dv = dinv[m0 + tid];
        }
        sdv[tid] = dv;
    }

    float acc[4][4][4];
#pragma unroll
    for (int i = 0; i < 4; i++)
#pragma unroll
        for (int j = 0; j < 4; j++)
#pragma unroll
            for (int e = 0; e < 4; e++) acc[i][j][e] = 0.0f;

    const uint32_t swz = (uint32_t)(lane & 7) << 4;
    uint32_t arow[4], brow[4];
#pragma unroll
    for (int t = 0; t < 4; t++) {
        arow[t] = (uint32_t)((wm * 64 + t * 16 + (lane & 15)) * 128);
        brow[t] = (uint32_t)((wn * 32 + t * 8 + (lane & 7)) * 128);
    }
    const uint32_t akh = (uint32_t)((lane >> 4) * 16);
    const uint32_t bkh = (uint32_t)(((lane >> 3) & 1) * 16);

    CPWAIT(0);
    __syncthreads();

#pragma unroll
    for (int ks = 0; ks < 8; ks++) {
        uint32_t kbo = (uint32_t)(ks >> 2) * 16384u;
        uint32_t axk = ((uint32_t)((ks & 3) * 32) + akh) ^ swz;
        uint32_t bxk = ((uint32_t)((ks & 3) * 32) + bkh) ^ swz;
        uint32_t ah[4][4], bh[4][2];
#pragma unroll
        for (int t = 0; t < 4; t++) {
            ldmx4(ah[t], sb + kbo + arow[t] + axk);
            ldmx2(bh[t], sb + 32768u + kbo + brow[t] + bxk);
        }
#pragma unroll
        for (int tm = 0; tm < 4; tm++)
#pragma unroll
            for (int tn = 0; tn < 4; tn++)
                mma16816(acc[tm][tn], ah[tm], bh[tn]);
    }

    float* sf = (float*)(smem + SF_OFF);   // [128][69]
    const int mc = tid & 63;
    const int mchunk = tid >> 6;

#pragma unroll
    for (int h = 0; h < 2; h++) {
        __syncthreads();
        if ((wn >> 1) == h) {
#pragma unroll
            for (int tm = 0; tm < 4; tm++) {
                int r0 = wm * 64 + tm * 16 + (lane >> 2);
                float d0 = sdv[r0], d1 = sdv[r0 + 8];
#pragma unroll
                for (int tn = 0; tn < 4; tn++) {
                    int cs = (wn & 1) * 32 + tn * 8 + 2 * (lane & 3);
                    sf[r0 * 69 + cs]           = d0 * acc[tm][tn][0];
                    sf[r0 * 69 + cs + 1]       = d0 * acc[tm][tn][1];
                    sf[(r0 + 8) * 69 + cs]     = d1 * acc[tm][tn][2];
                    sf[(r0 + 8) * 69 + cs + 1] = d1 * acc[tm][tn][3];
                }
            }
        }
        __syncthreads();

        float w[32];
#pragma unroll
        for (int c = 0; c < 32; c++)
            w[c] = sf[(mchunk * 32 + c) * 69 + mc];
        bf16* mrow = yth + (size_t)(h * 64 + mc) * MM + m0 + mchunk * 32;
#pragma unroll
        for (int q = 0; q < 4; q++) {
            uint4 o;
            o.x = pkh(w[q*8+0], w[q*8+1]); o.y = pkh(w[q*8+2], w[q*8+3]);
            o.z = pkh(w[q*8+4], w[q*8+5]); o.w = pkh(w[q*8+6], w[q*8+7]);
            *(uint4*)(mrow + q * 8) = o;
        }
    }
}

// ------------------------ small elementwise kernels ------------------------
__global__ __launch_bounds__(256) void cvt_h(const float* __restrict__ s,
                                             bf16* __restrict__ dh, int n4)
{
    int i = blockIdx.x * 256 + threadIdx.x;
    if (i >= n4) return;
    float4 v = ((const float4*)s)[i];
    ((uint2*)dh)[i] = make_uint2(pkh(v.x, v.y), pkh(v.z, v.w));
}

__global__ void tcvtW(const float* __restrict__ s1, bf16* __restrict__ d1,
                      const float* __restrict__ s2, bf16* __restrict__ d2)
{
    __shared__ float t[32][33];
    const float* src = blockIdx.z ? s2 : s1;
    bf16* dst = blockIdx.z ? d2 : d1;
    int c0 = blockIdx.x * 32, r0 = blockIdx.y * 32;
    for (int i = threadIdx.y; i < 32; i += 8)
        t[i][threadIdx.x] = src[(size_t)(r0 + i) * DD + c0 + threadIdx.x];
    __syncthreads();
    for (int i = threadIdx.y; i < 32; i += 8)
        dst[(size_t)(c0 + i) * DD + r0 + threadIdx.x] = __float2bfloat16(t[threadIdx.x][i]);
}

__global__ void tcvt_h(const float* __restrict__ src, bf16* __restrict__ dh,
                       int R, int C)
{
    __shared__ float t[32][33];
    int c0 = blockIdx.x * 32, r0 = blockIdx.y * 32;
    for (int i = threadIdx.y; i < 32; i += 8)
        t[i][threadIdx.x] = src[(size_t)(r0 + i) * C + c0 + threadIdx.x];
    __syncthreads();
    for (int i = threadIdx.y; i < 32; i += 8)
        dh[(size_t)(c0 + i) * R + r0 + threadIdx.x] = __float2bfloat16(t[threadIdx.x][i]);
}

__global__ __launch_bounds__(256) void up_combine8(const float* __restrict__ part,
    const float* __restrict__ bup, bf16* __restrict__ xh)
{
    int idx = blockIdx.x * 256 + threadIdx.x;
    int base = idx * 4, row = base >> 7;
    float s0 = 0.0f, s1 = 0.0f, s2 = 0.0f, s3 = 0.0f;
#pragma unroll
    for (int p = 0; p < 8; p++) {
        float4 a = ((const float4*)(part + (size_t)p * NN * DD))[idx];
        s0 += a.x; s1 += a.y; s2 += a.z; s3 += a.w;
    }
    float bu = bup[row];
    ((uint2*)(xh + (size_t)NN * DD))[idx] =
        make_uint2(pkh(s0 + bu, s1 + bu), pkh(s2 + bu, s3 + bu));
}

__global__ __launch_bounds__(256) void buildA_rs(const float* __restrict__ A,
    bf16* __restrict__ Ph, float* __restrict__ rsA)
{
    __shared__ float red[256];
    const int i = blockIdx.x;
    const float4* src = (const float4*)(A + (size_t)i * NN);
    float s = 0.0f;
    for (int j4 = threadIdx.x; j4 < NN / 4; j4 += 256) {
        float4 v = src[j4];
        s += (v.x + v.y) + (v.z + v.w);
        uint2 h = make_uint2(pkh(v.x, v.y), pkh(v.z, v.w));
        size_t o0 = (size_t)i * MM + j4 * 4;
        *(uint2*)(Ph + o0) = h;
        *(uint2*)(Ph + o0 + NN) = h;
        *(uint2*)(Ph + (size_t)(i + NN) * MM + j4 * 4) = h;
    }
    red[threadIdx.x] = s;
    __syncthreads();
    for (int st = 128; st > 0; st >>= 1) {
        if (threadIdx.x < st) red[threadIdx.x] += red[threadIdx.x + st];
        __syncthreads();
    }
    if (threadIdx.x == 0) rsA[i] = red[0];
}

__global__ __launch_bounds__(256) void deg_init(const float* __restrict__ rsA,
    const float* __restrict__ degp, float* __restrict__ dinv)
{
    int i = blockIdx.x * 256 + threadIdx.x;
    float d;
    if (i < NN) {
        d = 2.0f * rsA[i];
    } else {
        d = rsA[i - NN];
#pragma unroll
        for (int s = 0; s < 32; s++) d += degp[(size_t)s * MM + i];
    }
    dinv[i] = d > 0.0f ? rsqrtf(d) : 0.0f;
}

// ---------------------------------------------------------------------------
extern "C" void kernel_launch(void* const* d_in, const int* in_sizes, int n_in,
                              void* d_out, int out_size)
{
    const float* X   = (const float*)d_in[0];
    const float* A   = (const float*)d_in[1];
    const float* Wup = (const float*)d_in[2];
    const float* bup = (const float*)d_in[3];
    const float* W1  = (const float*)d_in[4];
    const float* b1  = (const float*)d_in[5];
    const float* W2  = (const float*)d_in[6];
    const float* b2  = (const float*)d_in[7];
    float* P = (float*)d_out;

    bf16 *Phi, *Xuh, *Yth, *Xth, *W1h, *W2h, *Wuh;
    float *part, *degp, *dinv, *rsA;
    unsigned* cnt;
    cudaGetSymbolAddress((void**)&Phi, g_Phi);
    cudaGetSymbolAddress((void**)&Xuh, g_Xuh);
    cudaGetSymbolAddress((void**)&Yth, g_Yth);
    cudaGetSymbolAddress((void**)&Xth, g_Xth);
    cudaGetSymbolAddress((void**)&W1h, g_W1h);
    cudaGetSymbolAddress((void**)&W2h, g_W2h);
    cudaGetSymbolAddress((void**)&Wuh, g_Wuh);
    cudaGetSymbolAddress((void**)&part, g_part);
    cudaGetSymbolAddress((void**)&degp, g_degp);
    cudaGetSymbolAddress((void**)&dinv, g_dinv);
    cudaGetSymbolAddress((void**)&rsA, g_rsA);
    cudaGetSymbolAddress((void**)&cnt, g_cnt);

    cudaFuncSetAttribute(adj_single, cudaFuncAttributeMaxDynamicSharedMemorySize, SGL_SMEM);
    cudaFuncSetAttribute(xxt_single, cudaFuncAttributeMaxDynamicSharedMemorySize, XXT_SMEM);
    cudaFuncSetAttribute(smallw, cudaFuncAttributeMaxDynamicSharedMemorySize, XXT_SMEM);

    // ---- init conversions ----
    cvt_h<<<(NN * DD / 4 + 255) / 256, 256>>>(X, Xuh, NN * DD / 4);
    tcvt_h<<<dim3(DD / 32, NN / 32), dim3(32, 8)>>>(X, Xth, NN, DD);
    cvt_h<<<(NN * NN / 4 + 255) / 256, 256>>>(Wup, Wuh, NN * NN / 4);
    tcvtW<<<dim3(4, 4, 2), dim3(32, 8)>>>(W1, W1h, W2, W2h);

    // new_nodes = Wup @ X (+ bup), ksplit=8 for full occupancy
    adj_single<<<dim3(NN / 128, 8), 256, SGL_SMEM>>>(Wuh, NN, Xth, NN,
        part, NN / 8, NN * DD, nullptr, nullptr, nullptr, nullptr);
    up_combine8<<<NN * DD / 4 / 256, 256>>>(part, bup, Xuh);

    // initial block adjacency (bf16) + fused A row sums + S deg partials
    buildA_rs<<<NN, 256>>>(A, Phi, rsA);
    xxt_single<<<32 * 33 / 2, 256, XXT_SMEM>>>(Xuh + (size_t)NN * DD, NN, 32,
                                               Phi, nullptr, degp, 0);
    deg_init<<<MM / 256, 256>>>(rsA, degp, dinv);

    for (int it = 0; it < 3; it++) {
        // conv1 (dinv already in gmem from init / previous conv2's smallw)
        smallw<<<MM / 128, 256, XXT_SMEM>>>(Xuh, W1h, dinv, nullptr, Yth);
        adj_single<<<dim3(MM / 128, 4), 256, SGL_SMEM>>>(Phi, MM, Yth, MM,
            part, MM / 4, MM * DD, dinv, b1, Xuh, cnt);
        // mid-loop adjacency rebuild + fused deg partials
        xxt_single<<<64 * 65 / 2, 256, XXT_SMEM>>>(Xuh, 0, 64, Phi, nullptr, degp, 0);
        // conv2 (smallw folds deg_reduce: computes + publishes dinv)
        smallw<<<MM / 128, 256, XXT_SMEM>>>(Xuh, W2h, dinv, degp, Yth);
        adj_single<<<dim3(MM / 128, 4), 256, SGL_SMEM>>>(Phi, MM, Yth, MM,
            part, MM / 4, MM * DD, dinv, b2, Xuh, cnt);
    }

    // final A_out = sigmoid(Xu Xu^T) -> d_out (fp32)
    xxt_single<<<64 * 65 / 2, 256, XXT_SMEM>>>(Xuh, 0, 64, nullptr, P, nullptr, 1);

    (void)in_sizes; (void)n_in; (void)out_size;
}

// round 14
// speedup vs baseline: 1.1333x; 1.1333x over previous
#include <cuda_runtime.h>
#include <cuda_bf16.h>
#include <stdint.h>
#include <math.h>

#define NN 4096
#define MM 8192
#define DD 128

typedef __nv_bfloat16 bf16;

// ----------------- device scratch (no allocations allowed) -----------------
__device__ bf16  g_Phi[(size_t)MM * MM];
__device__ bf16  g_Xuh[MM * DD];
__device__ bf16  g_Yth[DD * MM];
__device__ bf16  g_Xth[DD * NN];
__device__ bf16  g_W1h[DD * DD];
__device__ bf16  g_W2h[DD * DD];
__device__ bf16  g_Wuh[(size_t)NN * NN];
__device__ float g_part[8 * NN * DD];
__device__ float g_degp[64 * MM];
__device__ float g_dinv[MM];
__device__ float g_rsA[NN];

// ----------------------------- helpers ------------------------------------
__device__ __forceinline__ uint32_t s2u(const void* p) {
    uint32_t a;
    asm("{ .reg .u64 t; cvta.to.shared.u64 t, %1; cvt.u32.u64 %0, t; }"
        : "=r"(a) : "l"(p));
    return a;
}
#define SW128(o) ((o) ^ (((o) >> 3) & 0x70))

#define CPA(dst, src) asm volatile( \
    "cp.async.cg.shared.global [%0], [%1], 16;" :: "r"(dst), "l"(src))
#define CPCOMMIT() asm volatile("cp.async.commit_group;" ::: "memory")
#define CPWAIT(n)  asm volatile("cp.async.wait_group %0;" :: "n"(n) : "memory")

__device__ __forceinline__ void ldmx4(uint32_t* r, uint32_t a) {
    asm volatile("ldmatrix.sync.aligned.m8n8.x4.shared.b16 {%0,%1,%2,%3}, [%4];"
        : "=r"(r[0]), "=r"(r[1]), "=r"(r[2]), "=r"(r[3]) : "r"(a));
}
__device__ __forceinline__ void ldmx2(uint32_t* r, uint32_t a) {
    asm volatile("ldmatrix.sync.aligned.m8n8.x2.shared.b16 {%0,%1}, [%2];"
        : "=r"(r[0]), "=r"(r[1]) : "r"(a));
}
__device__ __forceinline__ void mma16816(float* c, const uint32_t* a, const uint32_t* b) {
    asm volatile(
        "mma.sync.aligned.m16n8k16.row.col.f32.bf16.bf16.f32 "
        "{%0,%1,%2,%3}, {%4,%5,%6,%7}, {%8,%9}, {%0,%1,%2,%3};"
        : "+f"(c[0]), "+f"(c[1]), "+f"(c[2]), "+f"(c[3])
        : "r"(a[0]), "r"(a[1]), "r"(a[2]), "r"(a[3]), "r"(b[0]), "r"(b[1]));
}

__device__ __forceinline__ uint32_t pkh(float a, float b) {
    return (uint32_t)__bfloat16_as_ushort(__float2bfloat16(a)) |
           ((uint32_t)__bfloat16_as_ushort(__float2bfloat16(b)) << 16);
}
__device__ __forceinline__ float sigm(float x) {
    return __fdividef(1.0f, 1.0f + __expf(-x));
}

#define SGL_SMEM 65536
#define SF_OFF   65536
#define RED_OFF  (65536 + 128 * 69 * 4)
#define XXT_SMEM (65536 + 128 * 69 * 4 + 1024)

// ===========================================================================
// adj_single (bf16): part[y] = A @ B^T. CTA 128x128, 2 CTAs/SM, warps 64x32.
// ===========================================================================
__device__ __forceinline__ void sgl_load(uint32_t sb, uint32_t stage,
    const bf16* Ah, int lda, const bf16* Bh, int ldb, int m0, int k0, int tid)
{
    uint32_t base = sb + stage * 32768u;
#pragma unroll
    for (int p = 0; p < 8; p++) {
        int idx = tid + p * 256;
        int mat = idx >> 10, w = idx & 1023, r = w >> 3, cg = w & 7;
        const bf16* s = mat ? (Bh + (size_t)r * ldb + k0 + cg * 8)
                            : (Ah + (size_t)(m0 + r) * lda + k0 + cg * 8);
        CPA(base + mat * 16384u + SW128(r * 128 + cg * 16), s);
    }
}

__global__ __launch_bounds__(256, 2) void adj_single(
    const bf16* __restrict__ Ah, int lda,
    const bf16* __restrict__ Bh, int ldb,
    float* __restrict__ part, int kcta, int pstride)
{
    extern __shared__ char smem[];
    const uint32_t sb = s2u(smem);
    const int tid = threadIdx.x, wid = tid >> 5, lane = tid & 31;
    const int wm = wid & 1, wn = wid >> 1;
    const int m0 = blockIdx.x * 128;
    const int k0b = blockIdx.y * kcta;
    const int NT = kcta >> 6;

    float acc[4][4][4];
#pragma unroll
    for (int i = 0; i < 4; i++)
#pragma unroll
        for (int j = 0; j < 4; j++)
#pragma unroll
            for (int e = 0; e < 4; e++) acc[i][j][e] = 0.0f;

    const uint32_t swz = (uint32_t)(lane & 7) << 4;
    uint32_t arow[4], brow[4];
#pragma unroll
    for (int t = 0; t < 4; t++) {
        arow[t] = (uint32_t)((wm * 64 + t * 16 + (lane & 15)) * 128);
        brow[t] = (uint32_t)((wn * 32 + t * 8 + (lane & 7)) * 128);
    }
    const uint32_t akh = (uint32_t)((lane >> 4) * 16);
    const uint32_t bkh = (uint32_t)(((lane >> 3) & 1) * 16);

    sgl_load(sb, 0, Ah, lda, Bh, ldb, m0, k0b, tid);
    CPCOMMIT();

    for (int kt = 0; kt < NT; kt++) {
        if (kt + 1 < NT) {
            sgl_load(sb, (kt + 1) & 1, Ah, lda, Bh, ldb, m0, k0b + (kt + 1) * 64, tid);
            CPCOMMIT();
            CPWAIT(1);
        } else {
            CPWAIT(0);
        }
        __syncthreads();

        uint32_t st = sb + (uint32_t)(kt & 1) * 32768u;
#pragma unroll
        for (int ks = 0; ks < 4; ks++) {
            uint32_t axk = ((uint32_t)(ks * 32) + akh) ^ swz;
            uint32_t bxk = ((uint32_t)(ks * 32) + bkh) ^ swz;
            uint32_t ah[4][4], bh[4][2];
#pragma unroll
            for (int t = 0; t < 4; t++) {
                ldmx4(ah[t], st + arow[t] + axk);
                ldmx2(bh[t], st + 16384u + brow[t] + bxk);
            }
#pragma unroll
            for (int tm = 0; tm < 4; tm++)
#pragma unroll
                for (int tn = 0; tn < 4; tn++)
                    mma16816(acc[tm][tn], ah[tm], bh[tn]);
        }
        __syncthreads();
    }

    float* dst = part + (size_t)blockIdx.y * pstride + (size_t)m0 * 128;
#pragma unroll
    for (int tm = 0; tm < 4; tm++)
#pragma unroll
        for (int tn = 0; tn < 4; tn++) {
            int r0 = wm * 64 + tm * 16 + (lane >> 2);
            int c0 = wn * 32 + tn * 8 + 2 * (lane & 3);
            *(float2*)(dst + (size_t)r0 * 128 + c0) =
                make_float2(acc[tm][tn][0], acc[tm][tn][1]);
            *(float2*)(dst + (size_t)(r0 + 8) * 128 + c0) =
                make_float2(acc[tm][tn][2], acc[tm][tn][3]);
        }
}

// ===========================================================================
// xxt_single: sigmoid(X X^T), X bf16 [n x 128], 128x128 tile pairs with
// DIAGONAL-LAST ordering. mode 0: bf16 into Ph (+mirror) + deg partials.
// mode 1: fp32 into Pf (+mirror).
// ===========================================================================
__global__ __launch_bounds__(256, 2) void xxt_single(
    const bf16* __restrict__ Xh, int ooff, int ndiag,
    bf16* __restrict__ Ph, float* __restrict__ Pf,
    float* __restrict__ degp, int mode)
{
    extern __shared__ char smem[];
    const uint32_t sb = s2u(smem);
    const int tid = threadIdx.x, wid = tid >> 5, lane = tid & 31;
    const int wm = wid & 1, wn = wid >> 1;

    int b = blockIdx.x;
    const int OFFD = ndiag * (ndiag - 1) / 2;
    int bi, bj;
    if (b < OFFD) {
        bj = (int)((1.0f + sqrtf(8.0f * (float)b + 1.0f)) * 0.5f);
        while (bj * (bj - 1) / 2 > b) bj--;
        while ((bj + 1) * bj / 2 <= b) bj++;
        bi = b - bj * (bj - 1) / 2;
    } else {
        bi = bj = b - OFFD;
    }

#pragma unroll
    for (int p = 0; p < 16; p++) {
        int idx = tid + p * 256;
        int mat = idx >> 11, w = idx & 2047, kb = w >> 10, ww = w & 1023;
        int r = ww >> 3, cg = ww & 7;
        int rb = (mat ? bj : bi) * 128;
        CPA(sb + (uint32_t)mat * 32768u + (uint32_t)kb * 16384u +
                SW128(r * 128 + cg * 16),
            Xh + (size_t)(rb + r) * 128 + kb * 64 + cg * 8);
    }
    CPCOMMIT();

    float acc[4][4][4];
#pragma unroll
    for (int i = 0; i < 4; i++)
#pragma unroll
        for (int j = 0; j < 4; j++)
#pragma unroll
            for (int e = 0; e < 4; e++) acc[i][j][e] = 0.0f;

    const uint32_t swz = (uint32_t)(lane & 7) << 4;
    uint32_t arow[4], brow[4];
#pragma unroll
    for (int t = 0; t < 4; t++) {
        arow[t] = (uint32_t)((wm * 64 + t * 16 + (lane & 15)) * 128);
        brow[t] = (uint32_t)((wn * 32 + t * 8 + (lane & 7)) * 128);
    }
    const uint32_t akh = (uint32_t)((lane >> 4) * 16);
    const uint32_t bkh = (uint32_t)(((lane >> 3) & 1) * 16);

    CPWAIT(0);
    __syncthreads();

#pragma unroll
    for (int ks = 0; ks < 8; ks++) {
        uint32_t kbo = (uint32_t)(ks >> 2) * 16384u;
        uint32_t axk = ((uint32_t)((ks & 3) * 32) + akh) ^ swz;
        uint32_t bxk = ((uint32_t)((ks & 3) * 32) + bkh) ^ swz;
        uint32_t ah[4][4], bh[4][2];
#pragma unroll
        for (int t = 0; t < 4; t++) {
            ldmx4(ah[t], sb + kbo + arow[t] + axk);
            ldmx2(bh[t], sb + 32768u + kbo + brow[t] + bxk);
        }
#pragma unroll
        for (int tm = 0; tm < 4; tm++)
#pragma unroll
            for (int tn = 0; tn < 4; tn++)
                mma16816(acc[tm][tn], ah[tm], bh[tn]);
    }

    const int gi0 = ooff + bi * 128;
    const int gj0 = ooff + bj * 128;
    float* sf = (float*)(smem + SF_OFF);      // [128][69]
    float* sred = (float*)(smem + RED_OFF);   // [256]

    float sdeg = 0.0f;

#pragma unroll
    for (int h = 0; h < 2; h++) {
        __syncthreads();
        if ((wn >> 1) == h) {
#pragma unroll
            for (int tm = 0; tm < 4; tm++)
#pragma unroll
                for (int tn = 0; tn < 4; tn++) {
                    int r0 = wm * 64 + tm * 16 + (lane >> 2);
                    int cs = (wn & 1) * 32 + tn * 8 + 2 * (lane & 3);
                    sf[r0 * 69 + cs]           = sigm(acc[tm][tn][0]);
                    sf[r0 * 69 + cs + 1]       = sigm(acc[tm][tn][1]);
                    sf[(r0 + 8) * 69 + cs]     = sigm(acc[tm][tn][2]);
                    sf[(r0 + 8) * 69 + cs + 1] = sigm(acc[tm][tn][3]);
                }
        }
        __syncthreads();

        if (mode == 0) {
            const int r = tid & 127;
            const int ch = (tid >> 7) * 32;
            float v[32];
#pragma unroll
            for (int c = 0; c < 32; c++) {
                v[c] = sf[r * 69 + ch + c];
                sdeg += v[c];
            }
            bf16* drow = Ph + (size_t)(gi0 + r) * MM + gj0 + h * 64 + ch;
#pragma unroll
            for (int q = 0; q < 4; q++) {
                uint4 o;
                o.x = pkh(v[q*8+0], v[q*8+1]); o.y = pkh(v[q*8+2], v[q*8+3]);
                o.z = pkh(v[q*8+4], v[q*8+5]); o.w = pkh(v[q*8+6], v[q*8+7]);
                *(uint4*)(drow + q * 8) = o;
            }
            if (bi != bj) {
                const int mc = tid & 63;
                const int mchunk = tid >> 6;
                float w[32];
                float ms = 0.0f;
#pragma unroll
                for (int c = 0; c < 32; c++) {
                    w[c] = sf[(mchunk * 32 + c) * 69 + mc];
                    ms += w[c];
                }
                bf16* mrow = Ph + (size_t)(gj0 + h * 64 + mc) * MM + gi0 + mchunk * 32;
#pragma unroll
                for (int q = 0; q < 4; q++) {
                    uint4 o;
                    o.x = pkh(w[q*8+0], w[q*8+1]); o.y = pkh(w[q*8+2], w[q*8+3]);
                    o.z = pkh(w[q*8+4], w[q*8+5]); o.w = pkh(w[q*8+6], w[q*8+7]);
                    *(uint4*)(mrow + q * 8) = o;
                }
                sred[tid] = ms;
                __syncthreads();
                if (degp && tid < 64)
                    degp[(size_t)bi * MM + gj0 + h * 64 + tid] =
                        sred[tid] + sred[tid + 64] + sred[tid + 128] + sred[tid + 192];
            }
        } else {
            const int r = tid >> 1;
            const int ch = (tid & 1) * 32;
            const int mc = tid >> 2;
            const int mchunk = tid & 3;
            float* drow = Pf + (size_t)(gi0 + r) * MM + gj0 + h * 64 + ch;
#pragma unroll
            for (int q = 0; q < 8; q++) {
                float4 o = make_float4(sf[r * 69 + ch + q*4], sf[r * 69 + ch + q*4+1],
                                       sf[r * 69 + ch + q*4+2], sf[r * 69 + ch + q*4+3]);
                *(float4*)(drow + q * 4) = o;
            }
            if (bi != bj) {
                float* mrow = Pf + (size_t)(gj0 + h * 64 + mc) * MM + gi0 + mchunk * 32;
#pragma unroll
                for (int q = 0; q < 8; q++) {
                    float4 o = make_float4(sf[(mchunk*32 + q*4+0) * 69 + mc],
                                           sf[(mchunk*32 + q*4+1) * 69 + mc],
                                           sf[(mchunk*32 + q*4+2) * 69 + mc],
                                           sf[(mchunk*32 + q*4+3) * 69 + mc]);
                    *(float4*)(mrow + q * 4) = o;
                }
            }
        }
    }

    if (mode == 0 && degp) {
        __syncthreads();
        sred[tid] = sdeg;
        __syncthreads();
        if (tid < 128)
            degp[(size_t)bj * MM + gi0 + tid] = sred[tid] + sred[tid + 128];
    }
}

// ===========================================================================
// smallw: Yth[c][j] = dinv[j] * (Xu[j,:] @ W^T[c,:]). Fused small GEMM +
// scale + transpose; optionally folds deg_reduce (degp != null).
// ===========================================================================
__global__ __launch_bounds__(256, 2) void smallw(
    const bf16* __restrict__ Xuh, const bf16* __restrict__ Wt,
    float* __restrict__ dinv, const float* __restrict__ degp,
    bf16* __restrict__ yth)
{
    extern __shared__ char smem[];
    const uint32_t sb = s2u(smem);
    const int tid = threadIdx.x, wid = tid >> 5, lane = tid & 31;
    const int wm = wid & 1, wn = wid >> 1;
    const int m0 = blockIdx.x * 128;
    float* sdv = (float*)(smem + RED_OFF);   // [128]

#pragma unroll
    for (int p = 0; p < 16; p++) {
        int idx = tid + p * 256;
        int mat = idx >> 11, w = idx & 2047, kb = w >> 10, ww = w & 1023;
        int r = ww >> 3, cg = ww & 7;
        const bf16* s = mat ? (Wt + (size_t)r * 128 + kb * 64 + cg * 8)
                            : (Xuh + (size_t)(m0 + r) * 128 + kb * 64 + cg * 8);
        CPA(sb + (uint32_t)mat * 32768u + (uint32_t)kb * 16384u +
                SW128(r * 128 + cg * 16), s);
    }
    CPCOMMIT();

    if (tid < 128) {
        float dv;
        if (degp) {
            float d = 0.0f;
#pragma unroll
            for (int s = 0; s < 64; s++) d += degp[(size_t)s * MM + m0 + tid];
            dv = d > 0.0f ? rsqrtf(d) : 0.0f;
            dinv[m0 + tid] = dv;
        } else {
            dv = dinv[m0 + tid];
        }
        sdv[tid] = dv;
    }

    float acc[4][4][4];
#pragma unroll
    for (int i = 0; i < 4; i++)
#pragma unroll
        for (int j = 0; j < 4; j++)
#pragma unroll
            for (int e = 0; e < 4; e++) acc[i][j][e] = 0.0f;

    const uint32_t swz = (uint32_t)(lane & 7) << 4;
    uint32_t arow[4], brow[4];
#pragma unroll
    for (int t = 0; t < 4; t++) {
        arow[t] = (uint32_t)((wm * 64 + t * 16 + (lane & 15)) * 128);
        brow[t] = (uint32_t)((wn * 32 + t * 8 + (lane & 7)) * 128);
    }
    const uint32_t akh = (uint32_t)((lane >> 4) * 16);
    const uint32_t bkh = (uint32_t)(((lane >> 3) & 1) * 16);

    CPWAIT(0);
    __syncthreads();

#pragma unroll
    for (int ks = 0; ks < 8; ks++) {
        uint32_t kbo = (uint32_t)(ks >> 2) * 16384u;
        uint32_t axk = ((uint32_t)((ks & 3) * 32) + akh) ^ swz;
        uint32_t bxk = ((uint32_t)((ks & 3) * 32) + bkh) ^ swz;
        uint32_t ah[4][4], bh[4][2];
#pragma unroll
        for (int t = 0; t < 4; t++) {
            ldmx4(ah[t], sb + kbo + arow[t] + axk);
            ldmx2(bh[t], sb + 32768u + kbo + brow[t] + bxk);
        }
#pragma unroll
        for (int tm = 0; tm < 4; tm++)
#pragma unroll
            for (int tn = 0; tn < 4; tn++)
                mma16816(acc[tm][tn], ah[tm], bh[tn]);
    }

    float* sf = (float*)(smem + SF_OFF);   // [128][69]
    const int mc = tid & 63;
    const int mchunk = tid >> 6;

#pragma unroll
    for (int h = 0; h < 2; h++) {
        __syncthreads();
        if ((wn >> 1) == h) {
#pragma unroll
            for (int tm = 0; tm < 4; tm++) {
                int r0 = wm * 64 + tm * 16 + (lane >> 2);
                float d0 = sdv[r0], d1 = sdv[r0 + 8];
#pragma unroll
                for (int tn = 0; tn < 4; tn++) {
                    int cs = (wn & 1) * 32 + tn * 8 + 2 * (lane & 3);
                    sf[r0 * 69 + cs]           = d0 * acc[tm][tn][0];
                    sf[r0 * 69 + cs + 1]       = d0 * acc[tm][tn][1];
                    sf[(r0 + 8) * 69 + cs]     = d1 * acc[tm][tn][2];
                    sf[(r0 + 8) * 69 + cs + 1] = d1 * acc[tm][tn][3];
                }
            }
        }
        __syncthreads();

        float w[32];
#pragma unroll
        for (int c = 0; c < 32; c++)
            w[c] = sf[(mchunk * 32 + c) * 69 + mc];
        bf16* mrow = yth + (size_t)(h * 64 + mc) * MM + m0 + mchunk * 32;
#pragma unroll
        for (int q = 0; q < 4; q++) {
            uint4 o;
            o.x = pkh(w[q*8+0], w[q*8+1]); o.y = pkh(w[q*8+2], w[q*8+3]);
            o.z = pkh(w[q*8+4], w[q*8+5]); o.w = pkh(w[q*8+6], w[q*8+7]);
            *(uint4*)(mrow + q * 8) = o;
        }
    }
}

// ------------------------ small elementwise kernels ------------------------
__global__ __launch_bounds__(256) void cvt_h(const float* __restrict__ s,
                                             bf16* __restrict__ dh, int n4)
{
    int i = blockIdx.x * 256 + threadIdx.x;
    if (i >= n4) return;
    float4 v = ((const float4*)s)[i];
    ((uint2*)dh)[i] = make_uint2(pkh(v.x, v.y), pkh(v.z, v.w));
}

// fused X conversion: one read of X -> row-major bf16 Xuh AND transposed Xth
__global__ void cvtX(const float* __restrict__ X, bf16* __restrict__ xuh,
                     bf16* __restrict__ xth)
{
    __shared__ float t[32][33];
    int c0 = blockIdx.x * 32, r0 = blockIdx.y * 32;
    for (int i = threadIdx.y; i < 32; i += 8) {
        float v = X[(size_t)(r0 + i) * DD + c0 + threadIdx.x];
        t[i][threadIdx.x] = v;
        xuh[(size_t)(r0 + i) * DD + c0 + threadIdx.x] = __float2bfloat16(v);
    }
    __syncthreads();
    for (int i = threadIdx.y; i < 32; i += 8)
        xth[(size_t)(c0 + i) * NN + r0 + threadIdx.x] =
            __float2bfloat16(t[threadIdx.x][i]);
}

__global__ void tcvtW(const float* __restrict__ s1, bf16* __restrict__ d1,
                      const float* __restrict__ s2, bf16* __restrict__ d2)
{
    __shared__ float t[32][33];
    const float* src = blockIdx.z ? s2 : s1;
    bf16* dst = blockIdx.z ? d2 : d1;
    int c0 = blockIdx.x * 32, r0 = blockIdx.y * 32;
    for (int i = threadIdx.y; i < 32; i += 8)
        t[i][threadIdx.x] = src[(size_t)(r0 + i) * DD + c0 + threadIdx.x];
    __syncthreads();
    for (int i = threadIdx.y; i < 32; i += 8)
        dst[(size_t)(c0 + i) * DD + r0 + threadIdx.x] = __float2bfloat16(t[threadIdx.x][i]);
}

__global__ __launch_bounds__(256) void xcombine4(const float* __restrict__ part,
    const float* __restrict__ dinv, const float* __restrict__ bias,
    bf16* __restrict__ xh)
{
    int idx = blockIdx.x * 256 + threadIdx.x;
    int base = idx * 4, row = base >> 7, c = base & 127;
    float4 a = ((const float4*)part)[idx];
    float4 b = ((const float4*)(part + (size_t)MM * DD))[idx];
    float4 d = ((const float4*)(part + (size_t)2 * MM * DD))[idx];
    float4 e = ((const float4*)(part + (size_t)3 * MM * DD))[idx];
    float di = dinv[row];
    float v0 = fmaxf(di * (a.x + b.x + d.x + e.x) + bias[c + 0], 0.0f);
    float v1 = fmaxf(di * (a.y + b.y + d.y + e.y) + bias[c + 1], 0.0f);
    float v2 = fmaxf(di * (a.z + b.z + d.z + e.z) + bias[c + 2], 0.0f);
    float v3 = fmaxf(di * (a.w + b.w + d.w + e.w) + bias[c + 3], 0.0f);
    ((uint2*)xh)[idx] = make_uint2(pkh(v0, v1), pkh(v2, v3));
}

__global__ __launch_bounds__(256) void up_combine8(const float* __restrict__ part,
    const float* __restrict__ bup, bf16* __restrict__ xh)
{
    int idx = blockIdx.x * 256 + threadIdx.x;
    int base = idx * 4, row = base >> 7;
    float s0 = 0.0f, s1 = 0.0f, s2 = 0.0f, s3 = 0.0f;
#pragma unroll
    for (int p = 0; p < 8; p++) {
        float4 a = ((const float4*)(part + (size_t)p * NN * DD))[idx];
        s0 += a.x; s1 += a.y; s2 += a.z; s3 += a.w;
    }
    float bu = bup[row];
    ((uint2*)(xh + (size_t)NN * DD))[idx] =
        make_uint2(pkh(s0 + bu, s1 + bu), pkh(s2 + bu, s3 + bu));
}

__global__ __launch_bounds__(256) void buildA_rs(const float* __restrict__ A,
    bf16* __restrict__ Ph, float* __restrict__ rsA)
{
    __shared__ float red[256];
    const int i = blockIdx.x;
    const float4* src = (const float4*)(A + (size_t)i * NN);
    float s = 0.0f;
    for (int j4 = threadIdx.x; j4 < NN / 4; j4 += 256) {
        float4 v = src[j4];
        s += (v.x + v.y) + (v.z + v.w);
        uint2 h = make_uint2(pkh(v.x, v.y), pkh(v.z, v.w));
        size_t o0 = (size_t)i * MM + j4 * 4;
        *(uint2*)(Ph + o0) = h;
        *(uint2*)(Ph + o0 + NN) = h;
        *(uint2*)(Ph + (size_t)(i + NN) * MM + j4 * 4) = h;
    }
    red[threadIdx.x] = s;
    __syncthreads();
    for (int st = 128; st > 0; st >>= 1) {
        if (threadIdx.x < st) red[threadIdx.x] += red[threadIdx.x + st];
        __syncthreads();
    }
    if (threadIdx.x == 0) rsA[i] = red[0];
}

__global__ __launch_bounds__(256) void deg_init(const float* __restrict__ rsA,
    const float* __restrict__ degp, float* __restrict__ dinv)
{
    int i = blockIdx.x * 256 + threadIdx.x;
    float d;
    if (i < NN) {
        d = 2.0f * rsA[i];
    } else {
        d = rsA[i - NN];
#pragma unroll
        for (int s = 0; s < 32; s++) d += degp[(size_t)s * MM + i];
    }
    dinv[i] = d > 0.0f ? rsqrtf(d) : 0.0f;
}

// ---------------------------------------------------------------------------
extern "C" void kernel_launch(void* const* d_in, const int* in_sizes, int n_in,
                              void* d_out, int out_size)
{
    const float* X   = (const float*)d_in[0];
    const float* A   = (const float*)d_in[1];
    const float* Wup = (const float*)d_in[2];
    const float* bup = (const float*)d_in[3];
    const float* W1  = (const float*)d_in[4];
    const float* b1  = (const float*)d_in[5];
    const float* W2  = (const float*)d_in[6];
    const float* b2  = (const float*)d_in[7];
    float* P = (float*)d_out;

    bf16 *Phi, *Xuh, *Yth, *Xth, *W1h, *W2h, *Wuh;
    float *part, *degp, *dinv, *rsA;
    cudaGetSymbolAddress((void**)&Phi, g_Phi);
    cudaGetSymbolAddress((void**)&Xuh, g_Xuh);
    cudaGetSymbolAddress((void**)&Yth, g_Yth);
    cudaGetSymbolAddress((void**)&Xth, g_Xth);
    cudaGetSymbolAddress((void**)&W1h, g_W1h);
    cudaGetSymbolAddress((void**)&W2h, g_W2h);
    cudaGetSymbolAddress((void**)&Wuh, g_Wuh);
    cudaGetSymbolAddress((void**)&part, g_part);
    cudaGetSymbolAddress((void**)&degp, g_degp);
    cudaGetSymbolAddress((void**)&dinv, g_dinv);
    cudaGetSymbolAddress((void**)&rsA, g_rsA);

    cudaFuncSetAttribute(adj_single, cudaFuncAttributeMaxDynamicSharedMemorySize, SGL_SMEM);
    cudaFuncSetAttribute(xxt_single, cudaFuncAttributeMaxDynamicSharedMemorySize, XXT_SMEM);
    cudaFuncSetAttribute(smallw, cudaFuncAttributeMaxDynamicSharedMemorySize, XXT_SMEM);

    // ---- init conversions ----
    cvtX<<<dim3(DD / 32, NN / 32), dim3(32, 8)>>>(X, Xuh, Xth);
    cvt_h<<<(NN * NN / 4 + 255) / 256, 256>>>(Wup, Wuh, NN * NN / 4);
    tcvtW<<<dim3(4, 4, 2), dim3(32, 8)>>>(W1, W1h, W2, W2h);

    // new_nodes = Wup @ X (+ bup), ksplit=8 for full occupancy
    adj_single<<<dim3(NN / 128, 8), 256, SGL_SMEM>>>(Wuh, NN, Xth, NN,
                                                     part, NN / 8, NN * DD);
    up_combine8<<<NN * DD / 4 / 256, 256>>>(part, bup, Xuh);

    // initial block adjacency (bf16) + fused A row sums + S deg partials
    buildA_rs<<<NN, 256>>>(A, Phi, rsA);
    xxt_single<<<32 * 33 / 2, 256, XXT_SMEM>>>(Xuh + (size_t)NN * DD, NN, 32,
                                               Phi, nullptr, degp, 0);
    deg_init<<<MM / 256, 256>>>(rsA, degp, dinv);

    for (int it = 0; it < 3; it++) {
        // conv1 (dinv already in gmem from init / previous conv2's smallw)
        smallw<<<MM / 128, 256, XXT_SMEM>>>(Xuh, W1h, dinv, nullptr, Yth);
        adj_single<<<dim3(MM / 128, 4), 256, SGL_SMEM>>>(Phi, MM, Yth, MM,
                                                         part, MM / 4, MM * DD);
        xcombine4<<<MM * DD / 4 / 256, 256>>>(part, dinv, b1, Xuh);
        // mid-loop adjacency rebuild + fused deg partials
        xxt_single<<<64 * 65 / 2, 256, XXT_SMEM>>>(Xuh, 0, 64, Phi, nullptr, degp, 0);
        // conv2 (smallw folds deg_reduce: computes + publishes dinv)
        smallw<<<MM / 128, 256, XXT_SMEM>>>(Xuh, W2h, dinv, degp, Yth);
        adj_single<<<dim3(MM / 128, 4), 256, SGL_SMEM>>>(Phi, MM, Yth, MM,
                                                         part, MM / 4, MM * DD);
        xcombine4<<<MM * DD / 4 / 256, 256>>>(part, dinv, b2, Xuh);
    }

    // final A_out = sigmoid(Xu Xu^T) -> d_out (fp32)
    xxt_single<<<64 * 65 / 2, 256, XXT_SMEM>>>(Xuh, 0, 64, nullptr, P, nullptr, 1);

    (void)in_sizes; (void)n_in; (void)out_size;
}